// round 14
// baseline (speedup 1.0000x reference)
#include <cuda_runtime.h>
#include <cuda_bf16.h>
#include <cstdint>

#define DEVFN __device__ __forceinline__

constexpr int NROWS  = 8192;
constexpr int DDIM   = 256;
constexpr int MT     = 128;          // tile size (rows and cols)
constexpr int NTILES = NROWS / MT;   // 64 column tiles
constexpr int NCTA   = 148;
constexpr int NTHREADS = 512;        // 16 warps = 2 independent tile-stream groups of 8
constexpr int JOBS_SYM = NTILES * (NTILES + 1) / 2;          // 2080
constexpr int JOBS_ALL = 2 * JOBS_SYM + NTILES * NTILES;     // 8256
constexpr float SQRT_SCALE = 1.6986436005760748f;  // sqrt(2*log2(e)), tau=0.5
constexpr float LN2F = 0.6931471805599453f;

// Scratch (device globals; no runtime allocation allowed)
__device__ __align__(16) __nv_bfloat16 Z1g[NROWS * DDIM];
__device__ __align__(16) __nv_bfloat16 Z2g[NROWS * DDIM];
__device__ float RSg[4][NROWS];   // row sums of exp for S11, S22, S12, S21
__device__ float DGg[3][NROWS];   // log2-domain diagonals

// ---------------- helpers ----------------
DEVFN uint32_t smem_u32(const void* p) {
    return (uint32_t)__cvta_generic_to_shared(p);
}
DEVFN float fexp2(float x) {
    float y;
    asm("ex2.approx.ftz.f32 %0, %1;" : "=f"(y) : "f"(x));
    return y;
}
DEVFN void ldm4(uint32_t& r0, uint32_t& r1, uint32_t& r2, uint32_t& r3, uint32_t addr) {
    asm volatile("ldmatrix.sync.aligned.m8n8.x4.shared.b16 {%0,%1,%2,%3}, [%4];"
                 : "=r"(r0), "=r"(r1), "=r"(r2), "=r"(r3) : "r"(addr));
}
DEVFN void mma_bf16(float* c, const uint32_t* a, uint32_t b0, uint32_t b1) {
    asm volatile(
        "mma.sync.aligned.m16n8k16.row.col.f32.bf16.bf16.f32 "
        "{%0,%1,%2,%3}, {%4,%5,%6,%7}, {%8,%9}, {%0,%1,%2,%3};"
        : "+f"(c[0]), "+f"(c[1]), "+f"(c[2]), "+f"(c[3])
        : "r"(a[0]), "r"(a[1]), "r"(a[2]), "r"(a[3]), "r"(b0), "r"(b1));
}
// mbarrier primitives (sm_80/90 base features)
DEVFN void mbar_init(uint32_t mbar, uint32_t cnt) {
    asm volatile("mbarrier.init.shared.b64 [%0], %1;" :: "r"(mbar), "r"(cnt) : "memory");
}
DEVFN void mbar_arrive(uint32_t mbar) {
    asm volatile("mbarrier.arrive.shared.b64 _, [%0];" :: "r"(mbar) : "memory");
}
// .noinc: async arrival decrements the pending count that init accounted for.
DEVFN void cp_mbar_arrive_noinc(uint32_t mbar) {
    asm volatile("cp.async.mbarrier.arrive.noinc.shared.b64 [%0];" :: "r"(mbar) : "memory");
}
DEVFN void mbar_wait(uint32_t mbar, uint32_t parity) {
    asm volatile(
        "{\n\t.reg .pred P;\n"
        "MW_%=:\n\t"
        "mbarrier.try_wait.parity.shared.b64 P, [%0], %1;\n\t"
        "@!P bra MW_%=;\n\t}"
        :: "r"(mbar), "r"(parity) : "memory");
}

// ---------------- SMEM layout ----------------
constexpr int SM_MBAR  = 0;      // full0, full1, empty0, empty1 (8B each)
constexpr int SM_A     = 1024;
constexpr int SM_B0    = SM_A  + 65536;
constexpr int SM_B1    = SM_B0 + 65536;
constexpr int SM_TOTAL = SM_B1 + 65536;   // 197632 B

// swizzled byte offset of (row, 16B-chunk) within a 128x256 bf16 tile
DEVFN uint32_t tile_off(int row, int chunk) {
    return (uint32_t)(row * 512 + ((((chunk & 7) ^ (row & 7))) << 4) + ((chunk & 24) << 4));
}

// Load a 128x256 bf16 tile into swizzled SMEM via cp.async, 256 threads (one group)
DEVFN void load_tile_g(uint32_t sdst, const __nv_bfloat16* __restrict__ src, int tig) {
    #pragma unroll
    for (int it = 0; it < 16; ++it) {
        int idx = tig + it * 256;           // 4096 chunks total
        int row = idx >> 5;                 // 0..127
        int c   = idx & 31;                 // chunk within row
        const __nv_bfloat16* gp = src + ((size_t)row << 8) + (c << 3);
        asm volatile("cp.async.cg.shared.global [%0], [%1], 16;"
                     :: "r"(sdst + tile_off(row, c)), "l"(gp) : "memory");
    }
}

// ---------------- Kernel 1: normalize (pre-scaled) + diagonals + RS zero ----------------
__global__ void __launch_bounds__(256) norm_kernel(const float* __restrict__ H1,
                                                   const float* __restrict__ H2) {
    if (blockIdx.x < 128) ((float*)RSg)[blockIdx.x * 256 + threadIdx.x] = 0.f;

    int row  = (blockIdx.x * 256 + threadIdx.x) >> 5;   // one row per warp
    int lane = threadIdx.x & 31;
    const float4* p1 = (const float4*)(H1 + (size_t)row * DDIM);
    const float4* p2 = (const float4*)(H2 + (size_t)row * DDIM);
    float4 x0 = p1[lane], x1 = p1[lane + 32];
    float4 y0 = p2[lane], y1 = p2[lane + 32];

    float ss1 = x0.x*x0.x + x0.y*x0.y + x0.z*x0.z + x0.w*x0.w
              + x1.x*x1.x + x1.y*x1.y + x1.z*x1.z + x1.w*x1.w;
    float ss2 = y0.x*y0.x + y0.y*y0.y + y0.z*y0.z + y0.w*y0.w
              + y1.x*y1.x + y1.y*y1.y + y1.z*y1.z + y1.w*y1.w;
    #pragma unroll
    for (int o = 16; o; o >>= 1) {
        ss1 += __shfl_xor_sync(0xFFFFFFFFu, ss1, o);
        ss2 += __shfl_xor_sync(0xFFFFFFFFu, ss2, o);
    }
    float inv1 = SQRT_SCALE / fmaxf(sqrtf(ss1), 1e-12f);
    float inv2 = SQRT_SCALE / fmaxf(sqrtf(ss2), 1e-12f);

    __nv_bfloat162 z1p[4], z2p[4];
    z1p[0] = __float22bfloat162_rn(make_float2(x0.x * inv1, x0.y * inv1));
    z1p[1] = __float22bfloat162_rn(make_float2(x0.z * inv1, x0.w * inv1));
    z1p[2] = __float22bfloat162_rn(make_float2(x1.x * inv1, x1.y * inv1));
    z1p[3] = __float22bfloat162_rn(make_float2(x1.z * inv1, x1.w * inv1));
    z2p[0] = __float22bfloat162_rn(make_float2(y0.x * inv2, y0.y * inv2));
    z2p[1] = __float22bfloat162_rn(make_float2(y0.z * inv2, y0.w * inv2));
    z2p[2] = __float22bfloat162_rn(make_float2(y1.x * inv2, y1.y * inv2));
    z2p[3] = __float22bfloat162_rn(make_float2(y1.z * inv2, y1.w * inv2));

    uint32_t* z1 = (uint32_t*)(Z1g + (size_t)row * DDIM);
    uint32_t* z2 = (uint32_t*)(Z2g + (size_t)row * DDIM);
    z1[2 * lane]          = *(uint32_t*)&z1p[0];
    z1[2 * lane + 1]      = *(uint32_t*)&z1p[1];
    z1[64 + 2 * lane]     = *(uint32_t*)&z1p[2];
    z1[64 + 2 * lane + 1] = *(uint32_t*)&z1p[3];
    z2[2 * lane]          = *(uint32_t*)&z2p[0];
    z2[2 * lane + 1]      = *(uint32_t*)&z2p[1];
    z2[64 + 2 * lane]     = *(uint32_t*)&z2p[2];
    z2[64 + 2 * lane + 1] = *(uint32_t*)&z2p[3];

    float d11 = 0.f, d22 = 0.f, d12 = 0.f;
    #pragma unroll
    for (int k = 0; k < 4; ++k) {
        float2 f1 = __bfloat1622float2(z1p[k]);
        float2 f2 = __bfloat1622float2(z2p[k]);
        d11 += f1.x * f1.x + f1.y * f1.y;
        d22 += f2.x * f2.x + f2.y * f2.y;
        d12 += f1.x * f2.x + f1.y * f2.y;
    }
    #pragma unroll
    for (int o = 16; o; o >>= 1) {
        d11 += __shfl_xor_sync(0xFFFFFFFFu, d11, o);
        d22 += __shfl_xor_sync(0xFFFFFFFFu, d22, o);
        d12 += __shfl_xor_sync(0xFFFFFFFFu, d12, o);
    }
    if (lane == 0) {
        DGg[0][row] = d11;   // log2-domain diagonals
        DGg[1][row] = d22;
        DGg[2][row] = d12;
    }
}

// ---------------- Kernel 2: two independent tile-stream groups (no mutex) -----------------
// 16 warps. Group g = wid>>3 (2 warps of each group per SMSP). Group g consumes tiles
// j0+g, j0+g+2, ... with its own B buffer (parity (j0+g)&1), its own full/empty barriers,
// and R9's proven 32x64 warp tile. Groups wait on different barriers -> natural anti-phase:
// one group's epilogue/refill runs under the other group's HMMA phase.
__global__ void __launch_bounds__(NTHREADS, 1) gram_kernel() {
    extern __shared__ char smem[];
    const uint32_t sb = smem_u32(smem);
    const int tid  = threadIdx.x;
    const int wid  = tid >> 5;
    const int lane = tid & 31;
    const int grp  = wid >> 3;        // tile-stream group
    const int w8   = wid & 7;         // warp within group
    const int wm   = w8 & 3;          // 32-row slice
    const int wn   = w8 >> 2;         // 64-col half
    const int tig  = tid & 255;       // thread id within group
    const int bx = blockIdx.x;

    const uint32_t mb_full[2]  = { sb + SM_MBAR,      sb + SM_MBAR + 8 };
    const uint32_t mb_empty[2] = { sb + SM_MBAR + 16, sb + SM_MBAR + 24 };
    if (tid == 0) {
        mbar_init(mb_full[0], 256);
        mbar_init(mb_full[1], 256);
        mbar_init(mb_empty[0], 8);
        mbar_init(mb_empty[1], 8);
    }
    int n_full[2]  = {0, 0};   // global completion counts per buffer
    int n_empty[2] = {0, 0};

    const int l7   = lane & 7;
    const int qA_r = (lane >> 3) & 1;
    const int qA_c = (lane >> 4);
    const int qB_r = (lane >> 4);
    const int qB_c = (lane >> 3) & 1;
    const int l3   = lane & 3;
    const int g4   = lane >> 2;

    const int start = bx * JOBS_ALL / NCTA;
    const int end   = (bx + 1) * JOBS_ALL / NCTA;

    // decode start -> (mat, rb, j)
    int mat, rb, j;
    {
        int idx = start;
        if (idx < JOBS_SYM)          { mat = 0; }
        else if (idx < 2 * JOBS_SYM) { mat = 1; idx -= JOBS_SYM; }
        else                         { mat = 2; idx -= 2 * JOBS_SYM; }
        if (mat < 2) {
            rb = 0;
            while (idx >= NTILES - rb) { idx -= NTILES - rb; ++rb; }
            j = rb + idx;
        } else { rb = idx >> 6; j = idx & 63; }
    }

    int remaining = end - start;

    while (remaining > 0) {
        const __nv_bfloat16 *X, *Y;
        int mrow, mcol; bool sym;
        if (mat == 0)      { X = Z1g; Y = Z1g; mrow = 0; mcol = 0; sym = true; }
        else if (mat == 1) { X = Z2g; Y = Z2g; mrow = 1; mcol = 1; sym = true; }
        else               { X = Z1g; Y = Z2g; mrow = 2; mcol = 3; sym = false; }

        const int j0 = j;
        const int seg = min(remaining, NTILES - j0);
        const int nt0 = (seg + 1) >> 1;       // tiles for group 0
        const int nt1 = seg >> 1;             // tiles for group 1
        const int ntg = grp ? nt1 : nt0;
        const int bg  = (j0 + grp) & 1;       // buffer owned by this group this segment
        const uint32_t bsm = bg ? sb + SM_B1 : sb + SM_B0;

        __syncthreads();   // previous segment fully done (both groups); orders mbar init

        float rs[4] = {0.f, 0.f, 0.f, 0.f};

        if (ntg > 0) {
            const int myfirst = j0 + grp;

            // prologue: this group loads full A + its first B tile, then one arrive each
            load_tile_g(sb + SM_A, X + (size_t)rb * MT * DDIM, tig);   // both groups write A (same data)
            load_tile_g(bsm, Y + (size_t)myfirst * MT * DDIM, tig);
            cp_mbar_arrive_noinc(mb_full[bg]);

            for (int i = 0; i < ntg; ++i) {
                const int jj = myfirst + 2 * i;

                mbar_wait(mb_full[bg], (uint32_t)((n_full[bg] + i) & 1));

                float acc[2][8][4];
                #pragma unroll
                for (int ms = 0; ms < 2; ++ms)
                    #pragma unroll
                    for (int ns = 0; ns < 8; ++ns)
                        #pragma unroll
                        for (int c = 0; c < 4; ++c) acc[ms][ns][c] = 0.f;

                #pragma unroll
                for (int ks = 0; ks < 16; ++ks) {
                    const int ch = 2 * ks;
                    uint32_t a0[4], a1[4];
                    {
                        int row = wm * 32 + l7 + 8 * qA_r;
                        ldm4(a0[0], a0[1], a0[2], a0[3], sb + SM_A + tile_off(row,      ch + qA_c));
                        ldm4(a1[0], a1[1], a1[2], a1[3], sb + SM_A + tile_off(row + 16, ch + qA_c));
                    }
                    uint32_t bf[4][4];
                    #pragma unroll
                    for (int np = 0; np < 4; ++np) {
                        int row = wn * 64 + np * 16 + l7 + 8 * qB_r;
                        ldm4(bf[np][0], bf[np][1], bf[np][2], bf[np][3],
                             bsm + tile_off(row, ch + qB_c));
                    }
                    #pragma unroll
                    for (int np = 0; np < 4; ++np)
                        #pragma unroll
                        for (int sub = 0; sub < 2; ++sub) {
                            mma_bf16(acc[0][2 * np + sub], a0, bf[np][2 * sub], bf[np][2 * sub + 1]);
                            mma_bf16(acc[1][2 * np + sub], a1, bf[np][2 * sub], bf[np][2 * sub + 1]);
                        }
                }

                if (lane == 0) mbar_arrive(mb_empty[bg]);

                // epilogue — overlaps the OTHER group's HMMA phase
                float col[16];
                #pragma unroll
                for (int c = 0; c < 16; ++c) col[c] = 0.f;
                #pragma unroll
                for (int ms = 0; ms < 2; ++ms)
                    #pragma unroll
                    for (int ns = 0; ns < 8; ++ns) {
                        float e0 = fexp2(acc[ms][ns][0]);
                        float e1 = fexp2(acc[ms][ns][1]);
                        float e2 = fexp2(acc[ms][ns][2]);
                        float e3 = fexp2(acc[ms][ns][3]);
                        rs[2 * ms]     += e0 + e1;
                        rs[2 * ms + 1] += e2 + e3;
                        col[2 * ns]     += e0 + e2;
                        col[2 * ns + 1] += e1 + e3;
                    }
                if (!sym || jj != rb) {
                    #pragma unroll
                    for (int c = 0; c < 16; ++c) {
                        col[c] += __shfl_xor_sync(0xFFFFFFFFu, col[c], 4);
                        col[c] += __shfl_xor_sync(0xFFFFFFFFu, col[c], 8);
                        col[c] += __shfl_xor_sync(0xFFFFFFFFu, col[c], 16);
                    }
                    if (lane < 4) {
                        float* dst = &RSg[mcol][jj * MT + wn * 64];
                        #pragma unroll
                        for (int ns = 0; ns < 8; ++ns) {
                            atomicAdd(dst + ns * 8 + 2 * lane,     col[2 * ns]);
                            atomicAdd(dst + ns * 8 + 2 * lane + 1, col[2 * ns + 1]);
                        }
                    }
                }

                // refill own buffer with tile jj+2 (also shadowed)
                if (i + 1 < ntg) {
                    mbar_wait(mb_empty[bg], (uint32_t)((n_empty[bg] + i) & 1));
                    load_tile_g(bsm, Y + (size_t)(jj + 2) * MT * DDIM, tig);
                    cp_mbar_arrive_noinc(mb_full[bg]);
                }
            }

            // flush row sums for this segment
            #pragma unroll
            for (int r = 0; r < 4; ++r) {
                rs[r] += __shfl_xor_sync(0xFFFFFFFFu, rs[r], 1);
                rs[r] += __shfl_xor_sync(0xFFFFFFFFu, rs[r], 2);
            }
            if (l3 == 0) {
                float* dst = &RSg[mrow][rb * MT + wm * 32];
                #pragma unroll
                for (int ms = 0; ms < 2; ++ms)
                    #pragma unroll
                    for (int cc = 0; cc < 2; ++cc)
                        atomicAdd(dst + ms * 16 + 8 * cc + g4, rs[2 * ms + cc]);
            }
        }

        // advance global barrier completion counts (uniform across all threads)
        {
            const int b0 = j0 & 1;           // group 0's buffer
            n_full[b0]     += nt0;  n_full[b0 ^ 1]  += nt1;
            n_empty[b0]    += nt0;  n_empty[b0 ^ 1] += nt1;
        }

        // advance schedule state
        remaining -= seg;
        j = j0 + seg;
        if (j == NTILES) {
            ++rb;
            if (mat < 2) {
                if (rb == NTILES) { ++mat; rb = 0; j = 0; }
                else j = rb;
            } else {
                j = 0;
            }
        }
    }
}

// ---------------- Kernel 3: final reduction ----------------
__global__ void __launch_bounds__(256) reduce_kernel(float* out) {
    float s = 0.f;
    for (int i = threadIdx.x; i < NROWS; i += 256) {
        float den1 = RSg[0][i] + RSg[2][i] - exp2f(DGg[0][i]);
        float den2 = RSg[1][i] + RSg[3][i] - exp2f(DGg[1][i]);
        s += 0.5f * (__logf(den1) + __logf(den2)) - DGg[2][i] * LN2F;
    }
    #pragma unroll
    for (int o = 16; o; o >>= 1) s += __shfl_xor_sync(0xFFFFFFFFu, s, o);
    __shared__ float ws[8];
    if ((threadIdx.x & 31) == 0) ws[threadIdx.x >> 5] = s;
    __syncthreads();
    if (threadIdx.x < 8) {
        s = ws[threadIdx.x];
        #pragma unroll
        for (int o = 4; o; o >>= 1) s += __shfl_xor_sync(0xFFu, s, o);
        if (threadIdx.x == 0) out[0] = s / (float)NROWS;
    }
}

// ---------------- launch ----------------
extern "C" void kernel_launch(void* const* d_in, const int* in_sizes, int n_in,
                              void* d_out, int out_size) {
    const float* H1 = (const float*)d_in[0];
    const float* H2 = (const float*)d_in[1];
    float* out = (float*)d_out;

    norm_kernel<<<NROWS * 32 / 256, 256>>>(H1, H2);

    static bool attr_set = false;
    if (!attr_set) {
        cudaFuncSetAttribute(gram_kernel, cudaFuncAttributeMaxDynamicSharedMemorySize, SM_TOTAL);
        attr_set = true;
    }
    gram_kernel<<<NCTA, NTHREADS, SM_TOTAL>>>();

    reduce_kernel<<<1, 256>>>(out);
}

// round 15
// speedup vs baseline: 1.0772x; 1.0772x over previous
#include <cuda_runtime.h>
#include <cuda_bf16.h>
#include <cstdint>

#define DEVFN __device__ __forceinline__

constexpr int NROWS  = 8192;
constexpr int DDIM   = 256;
constexpr int MT     = 128;          // tile size (rows and cols)
constexpr int NTILES = NROWS / MT;   // 64 column tiles
constexpr int NCTA   = 148;
constexpr int NTHREADS = 256;        // 8 warps: 4 row-slices x 2 col-halves (32x64 warp tile)
constexpr int JOBS_SYM = NTILES * (NTILES + 1) / 2;          // 2080
constexpr int JOBS_ALL = 2 * JOBS_SYM + NTILES * NTILES;     // 8256
constexpr float SQRT_SCALE = 1.6986436005760748f;  // sqrt(2*log2(e)), tau=0.5
constexpr float LN2F = 0.6931471805599453f;

// Scratch (device globals; no runtime allocation allowed)
__device__ __align__(16) __nv_bfloat16 Z1g[NROWS * DDIM];
__device__ __align__(16) __nv_bfloat16 Z2g[NROWS * DDIM];
__device__ float RSg[4][NROWS];   // row sums of exp for S11, S22, S12, S21
__device__ float DGg[3][NROWS];   // log2-domain diagonals

// ---------------- helpers ----------------
DEVFN uint32_t smem_u32(const void* p) {
    return (uint32_t)__cvta_generic_to_shared(p);
}
DEVFN float fexp2(float x) {
    float y;
    asm("ex2.approx.ftz.f32 %0, %1;" : "=f"(y) : "f"(x));
    return y;
}
DEVFN void ldm4(uint32_t& r0, uint32_t& r1, uint32_t& r2, uint32_t& r3, uint32_t addr) {
    asm volatile("ldmatrix.sync.aligned.m8n8.x4.shared.b16 {%0,%1,%2,%3}, [%4];"
                 : "=r"(r0), "=r"(r1), "=r"(r2), "=r"(r3) : "r"(addr));
}
DEVFN void mma_bf16(float* c, const uint32_t* a, uint32_t b0, uint32_t b1) {
    asm volatile(
        "mma.sync.aligned.m16n8k16.row.col.f32.bf16.bf16.f32 "
        "{%0,%1,%2,%3}, {%4,%5,%6,%7}, {%8,%9}, {%0,%1,%2,%3};"
        : "+f"(c[0]), "+f"(c[1]), "+f"(c[2]), "+f"(c[3])
        : "r"(a[0]), "r"(a[1]), "r"(a[2]), "r"(a[3]), "r"(b0), "r"(b1));
}
// mbarrier primitives (sm_80/90 base features)
DEVFN void mbar_init(uint32_t mbar, uint32_t cnt) {
    asm volatile("mbarrier.init.shared.b64 [%0], %1;" :: "r"(mbar), "r"(cnt) : "memory");
}
DEVFN void mbar_arrive(uint32_t mbar) {
    asm volatile("mbarrier.arrive.shared.b64 _, [%0];" :: "r"(mbar) : "memory");
}
// .noinc: async arrival decrements the pending count that init accounted for.
DEVFN void cp_mbar_arrive_noinc(uint32_t mbar) {
    asm volatile("cp.async.mbarrier.arrive.noinc.shared.b64 [%0];" :: "r"(mbar) : "memory");
}
DEVFN void mbar_wait(uint32_t mbar, uint32_t parity) {
    asm volatile(
        "{\n\t.reg .pred P;\n"
        "MW_%=:\n\t"
        "mbarrier.try_wait.parity.shared.b64 P, [%0], %1;\n\t"
        "@!P bra MW_%=;\n\t}"
        :: "r"(mbar), "r"(parity) : "memory");
}

// ---------------- SMEM layout ----------------
constexpr int SM_MBAR  = 0;      // full0, full1, empty0, empty1 (8B each)
constexpr int SM_A     = 1024;
constexpr int SM_B0    = SM_A  + 65536;
constexpr int SM_B1    = SM_B0 + 65536;
constexpr int SM_TOTAL = SM_B1 + 65536;   // 197632 B

// swizzled byte offset of (row, 16B-chunk) within a 128x256 bf16 tile
DEVFN uint32_t tile_off(int row, int chunk) {
    return (uint32_t)(row * 512 + ((((chunk & 7) ^ (row & 7))) << 4) + ((chunk & 24) << 4));
}

// Load a 128x256 bf16 tile into swizzled SMEM via cp.async (16B chunks), 256 threads
DEVFN void load_tile(uint32_t sdst, const __nv_bfloat16* __restrict__ src, int tid) {
    #pragma unroll
    for (int it = 0; it < 16; ++it) {
        int idx = tid + it * 256;           // 4096 chunks total
        int row = idx >> 5;                 // 0..127
        int c   = idx & 31;                 // chunk within row
        const __nv_bfloat16* gp = src + ((size_t)row << 8) + (c << 3);
        asm volatile("cp.async.cg.shared.global [%0], [%1], 16;"
                     :: "r"(sdst + tile_off(row, c)), "l"(gp) : "memory");
    }
}

// ---------------- Kernel 1: normalize (pre-scaled) + diagonals + RS zero ----------------
__global__ void __launch_bounds__(256) norm_kernel(const float* __restrict__ H1,
                                                   const float* __restrict__ H2) {
    if (blockIdx.x < 128) ((float*)RSg)[blockIdx.x * 256 + threadIdx.x] = 0.f;

    int row  = (blockIdx.x * 256 + threadIdx.x) >> 5;   // one row per warp
    int lane = threadIdx.x & 31;
    const float4* p1 = (const float4*)(H1 + (size_t)row * DDIM);
    const float4* p2 = (const float4*)(H2 + (size_t)row * DDIM);
    float4 x0 = p1[lane], x1 = p1[lane + 32];
    float4 y0 = p2[lane], y1 = p2[lane + 32];

    float ss1 = x0.x*x0.x + x0.y*x0.y + x0.z*x0.z + x0.w*x0.w
              + x1.x*x1.x + x1.y*x1.y + x1.z*x1.z + x1.w*x1.w;
    float ss2 = y0.x*y0.x + y0.y*y0.y + y0.z*y0.z + y0.w*y0.w
              + y1.x*y1.x + y1.y*y1.y + y1.z*y1.z + y1.w*y1.w;
    #pragma unroll
    for (int o = 16; o; o >>= 1) {
        ss1 += __shfl_xor_sync(0xFFFFFFFFu, ss1, o);
        ss2 += __shfl_xor_sync(0xFFFFFFFFu, ss2, o);
    }
    float inv1 = SQRT_SCALE / fmaxf(sqrtf(ss1), 1e-12f);
    float inv2 = SQRT_SCALE / fmaxf(sqrtf(ss2), 1e-12f);

    __nv_bfloat162 z1p[4], z2p[4];
    z1p[0] = __float22bfloat162_rn(make_float2(x0.x * inv1, x0.y * inv1));
    z1p[1] = __float22bfloat162_rn(make_float2(x0.z * inv1, x0.w * inv1));
    z1p[2] = __float22bfloat162_rn(make_float2(x1.x * inv1, x1.y * inv1));
    z1p[3] = __float22bfloat162_rn(make_float2(x1.z * inv1, x1.w * inv1));
    z2p[0] = __float22bfloat162_rn(make_float2(y0.x * inv2, y0.y * inv2));
    z2p[1] = __float22bfloat162_rn(make_float2(y0.z * inv2, y0.w * inv2));
    z2p[2] = __float22bfloat162_rn(make_float2(y1.x * inv2, y1.y * inv2));
    z2p[3] = __float22bfloat162_rn(make_float2(y1.z * inv2, y1.w * inv2));

    uint32_t* z1 = (uint32_t*)(Z1g + (size_t)row * DDIM);
    uint32_t* z2 = (uint32_t*)(Z2g + (size_t)row * DDIM);
    z1[2 * lane]          = *(uint32_t*)&z1p[0];
    z1[2 * lane + 1]      = *(uint32_t*)&z1p[1];
    z1[64 + 2 * lane]     = *(uint32_t*)&z1p[2];
    z1[64 + 2 * lane + 1] = *(uint32_t*)&z1p[3];
    z2[2 * lane]          = *(uint32_t*)&z2p[0];
    z2[2 * lane + 1]      = *(uint32_t*)&z2p[1];
    z2[64 + 2 * lane]     = *(uint32_t*)&z2p[2];
    z2[64 + 2 * lane + 1] = *(uint32_t*)&z2p[3];

    float d11 = 0.f, d22 = 0.f, d12 = 0.f;
    #pragma unroll
    for (int k = 0; k < 4; ++k) {
        float2 f1 = __bfloat1622float2(z1p[k]);
        float2 f2 = __bfloat1622float2(z2p[k]);
        d11 += f1.x * f1.x + f1.y * f1.y;
        d22 += f2.x * f2.x + f2.y * f2.y;
        d12 += f1.x * f2.x + f1.y * f2.y;
    }
    #pragma unroll
    for (int o = 16; o; o >>= 1) {
        d11 += __shfl_xor_sync(0xFFFFFFFFu, d11, o);
        d22 += __shfl_xor_sync(0xFFFFFFFFu, d22, o);
        d12 += __shfl_xor_sync(0xFFFFFFFFu, d12, o);
    }
    if (lane == 0) {
        DGg[0][row] = d11;   // log2-domain diagonals
        DGg[1][row] = d22;
        DGg[2][row] = d12;
    }
}

// ---------------- Kernel 2: R9 pipeline + A-fragments resident in registers --------------
// 8 warps, 32x64 warp tiles. A fragments (128 regs/thread) are loaded ONCE per segment and
// reused for all ~56 B tiles: cuts SMEM crossbar traffic per tile from 448KB to 320KB and
// removes 32 LDSM issues/warp/tile. 256 threads -> 255-reg budget, est ~235 used.
__global__ void __launch_bounds__(NTHREADS, 1) gram_kernel() {
    extern __shared__ char smem[];
    const uint32_t sb = smem_u32(smem);
    const int tid  = threadIdx.x;
    const int wid  = tid >> 5;
    const int lane = tid & 31;
    const int wm = wid & 3;
    const int wn = wid >> 2;
    const int bx = blockIdx.x;

    const uint32_t mb_full[2]  = { sb + SM_MBAR,      sb + SM_MBAR + 8 };
    const uint32_t mb_empty[2] = { sb + SM_MBAR + 16, sb + SM_MBAR + 24 };
    if (tid == 0) {
        mbar_init(mb_full[0], NTHREADS);
        mbar_init(mb_full[1], NTHREADS);
        mbar_init(mb_empty[0], 8);
        mbar_init(mb_empty[1], 8);
    }
    int n_full[2]  = {0, 0};
    int n_empty[2] = {0, 0};

    const int l7   = lane & 7;
    const int qA_r = (lane >> 3) & 1;
    const int qA_c = (lane >> 4);
    const int qB_r = (lane >> 4);
    const int qB_c = (lane >> 3) & 1;
    const int l3   = lane & 3;
    const int g    = lane >> 2;

    const int start = bx * JOBS_ALL / NCTA;
    const int end   = (bx + 1) * JOBS_ALL / NCTA;

    // decode start -> (mat, rb, j)
    int mat, rb, j;
    {
        int idx = start;
        if (idx < JOBS_SYM)          { mat = 0; }
        else if (idx < 2 * JOBS_SYM) { mat = 1; idx -= JOBS_SYM; }
        else                         { mat = 2; idx -= 2 * JOBS_SYM; }
        if (mat < 2) {
            rb = 0;
            while (idx >= NTILES - rb) { idx -= NTILES - rb; ++rb; }
            j = rb + idx;
        } else { rb = idx >> 6; j = idx & 63; }
    }

    int remaining = end - start;

    while (remaining > 0) {
        const __nv_bfloat16 *X, *Y;
        int mrow, mcol; bool sym;
        if (mat == 0)      { X = Z1g; Y = Z1g; mrow = 0; mcol = 0; sym = true; }
        else if (mat == 1) { X = Z2g; Y = Z2g; mrow = 1; mcol = 1; sym = true; }
        else               { X = Z1g; Y = Z2g; mrow = 2; mcol = 3; sym = false; }

        const int j0 = j;
        const int seg = min(remaining, NTILES - j0);
        const int jend = j0 + seg;

        __syncthreads();   // all warps done with previous segment's A/B; orders mbar init

        // prologue: A + first (up to) two B tiles
        load_tile(sb + SM_A, X + (size_t)rb * MT * DDIM, tid);
        const int b0 = j0 & 1;
        {
            load_tile(b0 ? sb + SM_B1 : sb + SM_B0, Y + (size_t)j0 * MT * DDIM, tid);
            cp_mbar_arrive_noinc(mb_full[b0]);
            ++n_full[b0];
            if (j0 + 1 < jend) {
                const int b1 = b0 ^ 1;
                load_tile(b1 ? sb + SM_B1 : sb + SM_B0, Y + (size_t)(j0 + 1) * MT * DDIM, tid);
                cp_mbar_arrive_noinc(mb_full[b1]);
                ++n_full[b1];
            }
        }

        // Wait for buffer b0 (cp.async completion is in-order per thread, so A is
        // complete too), then hoist this warp's A fragments into registers for the
        // whole segment: af[ks][0..3] = rows wm*32..+16, af[ks][4..7] = +16 rows.
        mbar_wait(mb_full[b0], (uint32_t)((n_full[b0] - 1) & 1));
        uint32_t af[16][8];
        {
            const int rowA = wm * 32 + l7 + 8 * qA_r;
            #pragma unroll
            for (int ks = 0; ks < 16; ++ks) {
                const int ch = 2 * ks;
                ldm4(af[ks][0], af[ks][1], af[ks][2], af[ks][3],
                     sb + SM_A + tile_off(rowA,      ch + qA_c));
                ldm4(af[ks][4], af[ks][5], af[ks][6], af[ks][7],
                     sb + SM_A + tile_off(rowA + 16, ch + qA_c));
            }
        }

        float rs[4] = {0.f, 0.f, 0.f, 0.f};

        for (int jj = j0; jj < jend; ++jj) {
            const int b = jj & 1;
            const uint32_t bsm = b ? sb + SM_B1 : sb + SM_B0;

            // (idempotent for jj==j0: that phase already completed above)
            mbar_wait(mb_full[b], (uint32_t)((n_full[b] - 1) & 1));

            float acc[2][8][4];
            #pragma unroll
            for (int ms = 0; ms < 2; ++ms)
                #pragma unroll
                for (int ns = 0; ns < 8; ++ns)
                    #pragma unroll
                    for (int c = 0; c < 4; ++c) acc[ms][ns][c] = 0.f;

            #pragma unroll
            for (int ks = 0; ks < 16; ++ks) {
                const int ch = 2 * ks;
                uint32_t bf[4][4];
                #pragma unroll
                for (int np = 0; np < 4; ++np) {
                    int row = wn * 64 + np * 16 + l7 + 8 * qB_r;
                    ldm4(bf[np][0], bf[np][1], bf[np][2], bf[np][3],
                         bsm + tile_off(row, ch + qB_c));
                }
                #pragma unroll
                for (int np = 0; np < 4; ++np)
                    #pragma unroll
                    for (int sub = 0; sub < 2; ++sub) {
                        mma_bf16(acc[0][2 * np + sub], &af[ks][0],
                                 bf[np][2 * sub], bf[np][2 * sub + 1]);
                        mma_bf16(acc[1][2 * np + sub], &af[ks][4],
                                 bf[np][2 * sub], bf[np][2 * sub + 1]);
                    }
            }

            if (lane == 0) mbar_arrive(mb_empty[b]);
            ++n_empty[b];

            // epilogue (overlaps other warps' MMA phase)
            float col[16];
            #pragma unroll
            for (int k = 0; k < 16; ++k) col[k] = 0.f;
            #pragma unroll
            for (int ms = 0; ms < 2; ++ms)
                #pragma unroll
                for (int ns = 0; ns < 8; ++ns) {
                    float e0 = fexp2(acc[ms][ns][0]);
                    float e1 = fexp2(acc[ms][ns][1]);
                    float e2 = fexp2(acc[ms][ns][2]);
                    float e3 = fexp2(acc[ms][ns][3]);
                    rs[2 * ms]     += e0 + e1;
                    rs[2 * ms + 1] += e2 + e3;
                    col[2 * ns]     += e0 + e2;
                    col[2 * ns + 1] += e1 + e3;
                }
            if (!sym || jj != rb) {
                #pragma unroll
                for (int k = 0; k < 16; ++k) {
                    col[k] += __shfl_xor_sync(0xFFFFFFFFu, col[k], 4);
                    col[k] += __shfl_xor_sync(0xFFFFFFFFu, col[k], 8);
                    col[k] += __shfl_xor_sync(0xFFFFFFFFu, col[k], 16);
                }
                if (lane < 4) {
                    float* dst = &RSg[mcol][jj * MT + wn * 64];
                    #pragma unroll
                    for (int ns = 0; ns < 8; ++ns) {
                        atomicAdd(dst + ns * 8 + 2 * lane,     col[2 * ns]);
                        atomicAdd(dst + ns * 8 + 2 * lane + 1, col[2 * ns + 1]);
                    }
                }
            }

            // producer: refill this buffer with tile jj+2
            if (jj + 2 < jend) {
                mbar_wait(mb_empty[b], (uint32_t)((n_empty[b] - 1) & 1));
                load_tile(bsm, Y + (size_t)(jj + 2) * MT * DDIM, tid);
                cp_mbar_arrive_noinc(mb_full[b]);
                ++n_full[b];
            }
        }

        // flush row sums for this segment
        #pragma unroll
        for (int r = 0; r < 4; ++r) {
            rs[r] += __shfl_xor_sync(0xFFFFFFFFu, rs[r], 1);
            rs[r] += __shfl_xor_sync(0xFFFFFFFFu, rs[r], 2);
        }
        if (l3 == 0) {
            float* dst = &RSg[mrow][rb * MT + wm * 32];
            #pragma unroll
            for (int ms = 0; ms < 2; ++ms)
                #pragma unroll
                for (int cc = 0; cc < 2; ++cc)
                    atomicAdd(dst + ms * 16 + 8 * cc + g, rs[2 * ms + cc]);
        }

        // advance schedule state
        remaining -= seg;
        j = jend;
        if (j == NTILES) {
            ++rb;
            if (mat < 2) {
                if (rb == NTILES) { ++mat; rb = 0; j = 0; }
                else j = rb;
            } else {
                j = 0;
            }
        }
    }
}

// ---------------- Kernel 3: final reduction ----------------
__global__ void __launch_bounds__(256) reduce_kernel(float* out) {
    float s = 0.f;
    for (int i = threadIdx.x; i < NROWS; i += 256) {
        float den1 = RSg[0][i] + RSg[2][i] - exp2f(DGg[0][i]);
        float den2 = RSg[1][i] + RSg[3][i] - exp2f(DGg[1][i]);
        s += 0.5f * (__logf(den1) + __logf(den2)) - DGg[2][i] * LN2F;
    }
    #pragma unroll
    for (int o = 16; o; o >>= 1) s += __shfl_xor_sync(0xFFFFFFFFu, s, o);
    __shared__ float ws[8];
    if ((threadIdx.x & 31) == 0) ws[threadIdx.x >> 5] = s;
    __syncthreads();
    if (threadIdx.x < 8) {
        s = ws[threadIdx.x];
        #pragma unroll
        for (int o = 4; o; o >>= 1) s += __shfl_xor_sync(0xFFu, s, o);
        if (threadIdx.x == 0) out[0] = s / (float)NROWS;
    }
}

// ---------------- launch ----------------
extern "C" void kernel_launch(void* const* d_in, const int* in_sizes, int n_in,
                              void* d_out, int out_size) {
    const float* H1 = (const float*)d_in[0];
    const float* H2 = (const float*)d_in[1];
    float* out = (float*)d_out;

    norm_kernel<<<NROWS * 32 / 256, 256>>>(H1, H2);

    static bool attr_set = false;
    if (!attr_set) {
        cudaFuncSetAttribute(gram_kernel, cudaFuncAttributeMaxDynamicSharedMemorySize, SM_TOTAL);
        attr_set = true;
    }
    gram_kernel<<<NCTA, NTHREADS, SM_TOTAL>>>();

    reduce_kernel<<<1, 256>>>(out);
}

// round 16
// speedup vs baseline: 1.1818x; 1.0971x over previous
#include <cuda_runtime.h>
#include <cuda_bf16.h>
#include <cstdint>

#define DEVFN __device__ __forceinline__

constexpr int NROWS  = 8192;
constexpr int DDIM   = 256;
constexpr int MT     = 128;          // tile size (rows and cols)
constexpr int NTILES = NROWS / MT;   // 64 column tiles
constexpr int NCTA   = 152;          // GB300 has 152 SMs (not 148)
constexpr int NTHREADS = 256;        // 8 warps: 4 row-slices x 2 col-halves (32x64 warp tile)
constexpr int JOBS_SYM = NTILES * (NTILES + 1) / 2;          // 2080
constexpr int JOBS_ALL = 2 * JOBS_SYM + NTILES * NTILES;     // 8256
constexpr float SQRT_SCALE = 1.6986436005760748f;  // sqrt(2*log2(e)), tau=0.5
constexpr float LN2F = 0.6931471805599453f;

// Scratch (device globals; no runtime allocation allowed)
__device__ __align__(16) __nv_bfloat16 Z1g[NROWS * DDIM];
__device__ __align__(16) __nv_bfloat16 Z2g[NROWS * DDIM];
__device__ float RSg[4][NROWS];   // row sums of exp for S11, S22, S12, S21
__device__ float DGg[3][NROWS];   // log2-domain diagonals

// ---------------- helpers ----------------
DEVFN uint32_t smem_u32(const void* p) {
    return (uint32_t)__cvta_generic_to_shared(p);
}
DEVFN float fexp2(float x) {
    float y;
    asm("ex2.approx.ftz.f32 %0, %1;" : "=f"(y) : "f"(x));
    return y;
}
DEVFN void ldm4(uint32_t& r0, uint32_t& r1, uint32_t& r2, uint32_t& r3, uint32_t addr) {
    asm volatile("ldmatrix.sync.aligned.m8n8.x4.shared.b16 {%0,%1,%2,%3}, [%4];"
                 : "=r"(r0), "=r"(r1), "=r"(r2), "=r"(r3) : "r"(addr));
}
DEVFN void mma_bf16(float* c, const uint32_t* a, uint32_t b0, uint32_t b1) {
    asm volatile(
        "mma.sync.aligned.m16n8k16.row.col.f32.bf16.bf16.f32 "
        "{%0,%1,%2,%3}, {%4,%5,%6,%7}, {%8,%9}, {%0,%1,%2,%3};"
        : "+f"(c[0]), "+f"(c[1]), "+f"(c[2]), "+f"(c[3])
        : "r"(a[0]), "r"(a[1]), "r"(a[2]), "r"(a[3]), "r"(b0), "r"(b1));
}
// mbarrier primitives (sm_80/90 base features)
DEVFN void mbar_init(uint32_t mbar, uint32_t cnt) {
    asm volatile("mbarrier.init.shared.b64 [%0], %1;" :: "r"(mbar), "r"(cnt) : "memory");
}
DEVFN void mbar_arrive(uint32_t mbar) {
    asm volatile("mbarrier.arrive.shared.b64 _, [%0];" :: "r"(mbar) : "memory");
}
// .noinc: async arrival decrements the pending count that init accounted for.
DEVFN void cp_mbar_arrive_noinc(uint32_t mbar) {
    asm volatile("cp.async.mbarrier.arrive.noinc.shared.b64 [%0];" :: "r"(mbar) : "memory");
}
DEVFN void mbar_wait(uint32_t mbar, uint32_t parity) {
    asm volatile(
        "{\n\t.reg .pred P;\n"
        "MW_%=:\n\t"
        "mbarrier.try_wait.parity.shared.b64 P, [%0], %1;\n\t"
        "@!P bra MW_%=;\n\t}"
        :: "r"(mbar), "r"(parity) : "memory");
}

// ---------------- SMEM layout ----------------
constexpr int SM_MBAR  = 0;      // full0, full1, empty0, empty1 (8B each)
constexpr int SM_A     = 1024;
constexpr int SM_B0    = SM_A  + 65536;
constexpr int SM_B1    = SM_B0 + 65536;
constexpr int SM_TOTAL = SM_B1 + 65536;   // 197632 B

// swizzled byte offset of (row, 16B-chunk) within a 128x256 bf16 tile
DEVFN uint32_t tile_off(int row, int chunk) {
    return (uint32_t)(row * 512 + ((((chunk & 7) ^ (row & 7))) << 4) + ((chunk & 24) << 4));
}

// Load a 128x256 bf16 tile into swizzled SMEM via cp.async (16B chunks), 256 threads
DEVFN void load_tile(uint32_t sdst, const __nv_bfloat16* __restrict__ src, int tid) {
    #pragma unroll
    for (int it = 0; it < 16; ++it) {
        int idx = tid + it * 256;           // 4096 chunks total
        int row = idx >> 5;                 // 0..127
        int c   = idx & 31;                 // chunk within row
        const __nv_bfloat16* gp = src + ((size_t)row << 8) + (c << 3);
        asm volatile("cp.async.cg.shared.global [%0], [%1], 16;"
                     :: "r"(sdst + tile_off(row, c)), "l"(gp) : "memory");
    }
}

// ---------------- Kernel 1: normalize (pre-scaled) + diagonals + RS zero ----------------
__global__ void __launch_bounds__(256) norm_kernel(const float* __restrict__ H1,
                                                   const float* __restrict__ H2) {
    if (blockIdx.x < 128) ((float*)RSg)[blockIdx.x * 256 + threadIdx.x] = 0.f;

    int row  = (blockIdx.x * 256 + threadIdx.x) >> 5;   // one row per warp
    int lane = threadIdx.x & 31;
    const float4* p1 = (const float4*)(H1 + (size_t)row * DDIM);
    const float4* p2 = (const float4*)(H2 + (size_t)row * DDIM);
    float4 x0 = p1[lane], x1 = p1[lane + 32];
    float4 y0 = p2[lane], y1 = p2[lane + 32];

    float ss1 = x0.x*x0.x + x0.y*x0.y + x0.z*x0.z + x0.w*x0.w
              + x1.x*x1.x + x1.y*x1.y + x1.z*x1.z + x1.w*x1.w;
    float ss2 = y0.x*y0.x + y0.y*y0.y + y0.z*y0.z + y0.w*y0.w
              + y1.x*y1.x + y1.y*y1.y + y1.z*y1.z + y1.w*y1.w;
    #pragma unroll
    for (int o = 16; o; o >>= 1) {
        ss1 += __shfl_xor_sync(0xFFFFFFFFu, ss1, o);
        ss2 += __shfl_xor_sync(0xFFFFFFFFu, ss2, o);
    }
    float inv1 = SQRT_SCALE / fmaxf(sqrtf(ss1), 1e-12f);
    float inv2 = SQRT_SCALE / fmaxf(sqrtf(ss2), 1e-12f);

    __nv_bfloat162 z1p[4], z2p[4];
    z1p[0] = __float22bfloat162_rn(make_float2(x0.x * inv1, x0.y * inv1));
    z1p[1] = __float22bfloat162_rn(make_float2(x0.z * inv1, x0.w * inv1));
    z1p[2] = __float22bfloat162_rn(make_float2(x1.x * inv1, x1.y * inv1));
    z1p[3] = __float22bfloat162_rn(make_float2(x1.z * inv1, x1.w * inv1));
    z2p[0] = __float22bfloat162_rn(make_float2(y0.x * inv2, y0.y * inv2));
    z2p[1] = __float22bfloat162_rn(make_float2(y0.z * inv2, y0.w * inv2));
    z2p[2] = __float22bfloat162_rn(make_float2(y1.x * inv2, y1.y * inv2));
    z2p[3] = __float22bfloat162_rn(make_float2(y1.z * inv2, y1.w * inv2));

    uint32_t* z1 = (uint32_t*)(Z1g + (size_t)row * DDIM);
    uint32_t* z2 = (uint32_t*)(Z2g + (size_t)row * DDIM);
    z1[2 * lane]          = *(uint32_t*)&z1p[0];
    z1[2 * lane + 1]      = *(uint32_t*)&z1p[1];
    z1[64 + 2 * lane]     = *(uint32_t*)&z1p[2];
    z1[64 + 2 * lane + 1] = *(uint32_t*)&z1p[3];
    z2[2 * lane]          = *(uint32_t*)&z2p[0];
    z2[2 * lane + 1]      = *(uint32_t*)&z2p[1];
    z2[64 + 2 * lane]     = *(uint32_t*)&z2p[2];
    z2[64 + 2 * lane + 1] = *(uint32_t*)&z2p[3];

    float d11 = 0.f, d22 = 0.f, d12 = 0.f;
    #pragma unroll
    for (int k = 0; k < 4; ++k) {
        float2 f1 = __bfloat1622float2(z1p[k]);
        float2 f2 = __bfloat1622float2(z2p[k]);
        d11 += f1.x * f1.x + f1.y * f1.y;
        d22 += f2.x * f2.x + f2.y * f2.y;
        d12 += f1.x * f2.x + f1.y * f2.y;
    }
    #pragma unroll
    for (int o = 16; o; o >>= 1) {
        d11 += __shfl_xor_sync(0xFFFFFFFFu, d11, o);
        d22 += __shfl_xor_sync(0xFFFFFFFFu, d22, o);
        d12 += __shfl_xor_sync(0xFFFFFFFFu, d12, o);
    }
    if (lane == 0) {
        DGg[0][row] = d11;   // log2-domain diagonals
        DGg[1][row] = d22;
        DGg[2][row] = d12;
    }
}

// ---------------- Kernel 2: R9 pipeline (proven best), flat schedule over 152 CTAs -------
// 8 warps, 32x64 warp tiles, mbarrier-pipelined double-buffered B, epilogue after MMA.
__global__ void __launch_bounds__(NTHREADS, 1) gram_kernel() {
    extern __shared__ char smem[];
    const uint32_t sb = smem_u32(smem);
    const int tid  = threadIdx.x;
    const int wid  = tid >> 5;
    const int lane = tid & 31;
    const int wm = wid & 3;
    const int wn = wid >> 2;
    const int bx = blockIdx.x;

    const uint32_t mb_full[2]  = { sb + SM_MBAR,      sb + SM_MBAR + 8 };
    const uint32_t mb_empty[2] = { sb + SM_MBAR + 16, sb + SM_MBAR + 24 };
    if (tid == 0) {
        mbar_init(mb_full[0], NTHREADS);
        mbar_init(mb_full[1], NTHREADS);
        mbar_init(mb_empty[0], 8);
        mbar_init(mb_empty[1], 8);
    }
    int n_full[2]  = {0, 0};
    int n_empty[2] = {0, 0};

    const int l7   = lane & 7;
    const int qA_r = (lane >> 3) & 1;
    const int qA_c = (lane >> 4);
    const int qB_r = (lane >> 4);
    const int qB_c = (lane >> 3) & 1;
    const int l3   = lane & 3;
    const int g    = lane >> 2;

    const int start = bx * JOBS_ALL / NCTA;
    const int end   = (bx + 1) * JOBS_ALL / NCTA;

    // decode start -> (mat, rb, j)
    int mat, rb, j;
    {
        int idx = start;
        if (idx < JOBS_SYM)          { mat = 0; }
        else if (idx < 2 * JOBS_SYM) { mat = 1; idx -= JOBS_SYM; }
        else                         { mat = 2; idx -= 2 * JOBS_SYM; }
        if (mat < 2) {
            rb = 0;
            while (idx >= NTILES - rb) { idx -= NTILES - rb; ++rb; }
            j = rb + idx;
        } else { rb = idx >> 6; j = idx & 63; }
    }

    int remaining = end - start;

    while (remaining > 0) {
        const __nv_bfloat16 *X, *Y;
        int mrow, mcol; bool sym;
        if (mat == 0)      { X = Z1g; Y = Z1g; mrow = 0; mcol = 0; sym = true; }
        else if (mat == 1) { X = Z2g; Y = Z2g; mrow = 1; mcol = 1; sym = true; }
        else               { X = Z1g; Y = Z2g; mrow = 2; mcol = 3; sym = false; }

        const int j0 = j;
        const int seg = min(remaining, NTILES - j0);
        const int jend = j0 + seg;

        __syncthreads();   // all warps done with previous segment's A/B; orders mbar init

        // prologue: A + first (up to) two B tiles
        load_tile(sb + SM_A, X + (size_t)rb * MT * DDIM, tid);
        {
            const int b0 = j0 & 1;
            load_tile(b0 ? sb + SM_B1 : sb + SM_B0, Y + (size_t)j0 * MT * DDIM, tid);
            cp_mbar_arrive_noinc(mb_full[b0]);
            ++n_full[b0];
            if (j0 + 1 < jend) {
                const int b1 = b0 ^ 1;
                load_tile(b1 ? sb + SM_B1 : sb + SM_B0, Y + (size_t)(j0 + 1) * MT * DDIM, tid);
                cp_mbar_arrive_noinc(mb_full[b1]);
                ++n_full[b1];
            }
        }

        float rs[4] = {0.f, 0.f, 0.f, 0.f};

        for (int jj = j0; jj < jend; ++jj) {
            const int b = jj & 1;
            const uint32_t bsm = b ? sb + SM_B1 : sb + SM_B0;

            mbar_wait(mb_full[b], (uint32_t)((n_full[b] - 1) & 1));

            float acc[2][8][4];
            #pragma unroll
            for (int ms = 0; ms < 2; ++ms)
                #pragma unroll
                for (int ns = 0; ns < 8; ++ns)
                    #pragma unroll
                    for (int c = 0; c < 4; ++c) acc[ms][ns][c] = 0.f;

            #pragma unroll
            for (int ks = 0; ks < 16; ++ks) {
                const int ch = 2 * ks;
                uint32_t a0[4], a1[4];
                {
                    int row = wm * 32 + l7 + 8 * qA_r;
                    ldm4(a0[0], a0[1], a0[2], a0[3], sb + SM_A + tile_off(row,      ch + qA_c));
                    ldm4(a1[0], a1[1], a1[2], a1[3], sb + SM_A + tile_off(row + 16, ch + qA_c));
                }
                uint32_t bf[4][4];
                #pragma unroll
                for (int np = 0; np < 4; ++np) {
                    int row = wn * 64 + np * 16 + l7 + 8 * qB_r;
                    ldm4(bf[np][0], bf[np][1], bf[np][2], bf[np][3],
                         bsm + tile_off(row, ch + qB_c));
                }
                #pragma unroll
                for (int np = 0; np < 4; ++np)
                    #pragma unroll
                    for (int sub = 0; sub < 2; ++sub) {
                        mma_bf16(acc[0][2 * np + sub], a0, bf[np][2 * sub], bf[np][2 * sub + 1]);
                        mma_bf16(acc[1][2 * np + sub], a1, bf[np][2 * sub], bf[np][2 * sub + 1]);
                    }
            }

            if (lane == 0) mbar_arrive(mb_empty[b]);
            ++n_empty[b];

            // epilogue (overlaps other warps' MMA phase)
            float col[16];
            #pragma unroll
            for (int k = 0; k < 16; ++k) col[k] = 0.f;
            #pragma unroll
            for (int ms = 0; ms < 2; ++ms)
                #pragma unroll
                for (int ns = 0; ns < 8; ++ns) {
                    float e0 = fexp2(acc[ms][ns][0]);
                    float e1 = fexp2(acc[ms][ns][1]);
                    float e2 = fexp2(acc[ms][ns][2]);
                    float e3 = fexp2(acc[ms][ns][3]);
                    rs[2 * ms]     += e0 + e1;
                    rs[2 * ms + 1] += e2 + e3;
                    col[2 * ns]     += e0 + e2;
                    col[2 * ns + 1] += e1 + e3;
                }
            if (!sym || jj != rb) {
                #pragma unroll
                for (int k = 0; k < 16; ++k) {
                    col[k] += __shfl_xor_sync(0xFFFFFFFFu, col[k], 4);
                    col[k] += __shfl_xor_sync(0xFFFFFFFFu, col[k], 8);
                    col[k] += __shfl_xor_sync(0xFFFFFFFFu, col[k], 16);
                }
                if (lane < 4) {
                    float* dst = &RSg[mcol][jj * MT + wn * 64];
                    #pragma unroll
                    for (int ns = 0; ns < 8; ++ns) {
                        atomicAdd(dst + ns * 8 + 2 * lane,     col[2 * ns]);
                        atomicAdd(dst + ns * 8 + 2 * lane + 1, col[2 * ns + 1]);
                    }
                }
            }

            // producer: refill this buffer with tile jj+2
            if (jj + 2 < jend) {
                mbar_wait(mb_empty[b], (uint32_t)((n_empty[b] - 1) & 1));
                load_tile(bsm, Y + (size_t)(jj + 2) * MT * DDIM, tid);
                cp_mbar_arrive_noinc(mb_full[b]);
                ++n_full[b];
            }
        }

        // flush row sums for this segment
        #pragma unroll
        for (int r = 0; r < 4; ++r) {
            rs[r] += __shfl_xor_sync(0xFFFFFFFFu, rs[r], 1);
            rs[r] += __shfl_xor_sync(0xFFFFFFFFu, rs[r], 2);
        }
        if (l3 == 0) {
            float* dst = &RSg[mrow][rb * MT + wm * 32];
            #pragma unroll
            for (int ms = 0; ms < 2; ++ms)
                #pragma unroll
                for (int cc = 0; cc < 2; ++cc)
                    atomicAdd(dst + ms * 16 + 8 * cc + g, rs[2 * ms + cc]);
        }

        // advance schedule state
        remaining -= seg;
        j = jend;
        if (j == NTILES) {
            ++rb;
            if (mat < 2) {
                if (rb == NTILES) { ++mat; rb = 0; j = 0; }
                else j = rb;
            } else {
                j = 0;
            }
        }
    }
}

// ---------------- Kernel 3: final reduction (1024 threads) ----------------
__global__ void __launch_bounds__(1024) reduce_kernel(float* out) {
    float s = 0.f;
    for (int i = threadIdx.x; i < NROWS; i += 1024) {
        float den1 = RSg[0][i] + RSg[2][i] - exp2f(DGg[0][i]);
        float den2 = RSg[1][i] + RSg[3][i] - exp2f(DGg[1][i]);
        s += 0.5f * (__logf(den1) + __logf(den2)) - DGg[2][i] * LN2F;
    }
    #pragma unroll
    for (int o = 16; o; o >>= 1) s += __shfl_xor_sync(0xFFFFFFFFu, s, o);
    __shared__ float ws[32];
    if ((threadIdx.x & 31) == 0) ws[threadIdx.x >> 5] = s;
    __syncthreads();
    if (threadIdx.x < 32) {
        s = ws[threadIdx.x];
        #pragma unroll
        for (int o = 16; o; o >>= 1) s += __shfl_xor_sync(0xFFFFFFFFu, s, o);
        if (threadIdx.x == 0) out[0] = s / (float)NROWS;
    }
}

// ---------------- launch ----------------
extern "C" void kernel_launch(void* const* d_in, const int* in_sizes, int n_in,
                              void* d_out, int out_size) {
    const float* H1 = (const float*)d_in[0];
    const float* H2 = (const float*)d_in[1];
    float* out = (float*)d_out;

    norm_kernel<<<NROWS * 32 / 256, 256>>>(H1, H2);

    static bool attr_set = false;
    if (!attr_set) {
        cudaFuncSetAttribute(gram_kernel, cudaFuncAttributeMaxDynamicSharedMemorySize, SM_TOTAL);
        attr_set = true;
    }
    gram_kernel<<<NCTA, NTHREADS, SM_TOTAL>>>();

    reduce_kernel<<<1, 1024>>>(out);
}

// round 17
// speedup vs baseline: 1.2244x; 1.0361x over previous
#include <cuda_runtime.h>
#include <cuda_bf16.h>
#include <cstdint>

#define DEVFN __device__ __forceinline__

constexpr int NROWS  = 8192;
constexpr int DDIM   = 256;
constexpr int MT     = 128;          // tile size (rows and cols)
constexpr int NTILES = NROWS / MT;   // 64 column tiles
constexpr int NCTA   = 152;          // GB300 has 152 SMs
constexpr int NTHREADS = 256;        // 8 warps: 4 row-slices x 2 col-halves (32x64 warp tile)
constexpr int JOBS_SYM = NTILES * (NTILES + 1) / 2;          // 2080 (= 32 pairs x 65)
constexpr int JOBS_ALL = 2 * JOBS_SYM + NTILES * NTILES;     // 8256
constexpr float SQRT_SCALE = 1.6986436005760748f;  // sqrt(2*log2(e)), tau=0.5
constexpr float LN2F = 0.6931471805599453f;

// Scratch (device globals; no runtime allocation allowed)
__device__ __align__(16) __nv_bfloat16 Z1g[NROWS * DDIM];
__device__ __align__(16) __nv_bfloat16 Z2g[NROWS * DDIM];
__device__ float RSg[4][NROWS];   // row sums of exp for S11, S22, S12, S21
__device__ float DGg[3][NROWS];   // log2-domain diagonals

// ---------------- helpers ----------------
DEVFN uint32_t smem_u32(const void* p) {
    return (uint32_t)__cvta_generic_to_shared(p);
}
DEVFN float fexp2(float x) {
    float y;
    asm("ex2.approx.ftz.f32 %0, %1;" : "=f"(y) : "f"(x));
    return y;
}
DEVFN void ldm4(uint32_t& r0, uint32_t& r1, uint32_t& r2, uint32_t& r3, uint32_t addr) {
    asm volatile("ldmatrix.sync.aligned.m8n8.x4.shared.b16 {%0,%1,%2,%3}, [%4];"
                 : "=r"(r0), "=r"(r1), "=r"(r2), "=r"(r3) : "r"(addr));
}
DEVFN void mma_bf16(float* c, const uint32_t* a, uint32_t b0, uint32_t b1) {
    asm volatile(
        "mma.sync.aligned.m16n8k16.row.col.f32.bf16.bf16.f32 "
        "{%0,%1,%2,%3}, {%4,%5,%6,%7}, {%8,%9}, {%0,%1,%2,%3};"
        : "+f"(c[0]), "+f"(c[1]), "+f"(c[2]), "+f"(c[3])
        : "r"(a[0]), "r"(a[1]), "r"(a[2]), "r"(a[3]), "r"(b0), "r"(b1));
}
// mbarrier primitives (sm_80/90 base features)
DEVFN void mbar_init(uint32_t mbar, uint32_t cnt) {
    asm volatile("mbarrier.init.shared.b64 [%0], %1;" :: "r"(mbar), "r"(cnt) : "memory");
}
DEVFN void mbar_arrive(uint32_t mbar) {
    asm volatile("mbarrier.arrive.shared.b64 _, [%0];" :: "r"(mbar) : "memory");
}
// .noinc: async arrival decrements the pending count that init accounted for.
DEVFN void cp_mbar_arrive_noinc(uint32_t mbar) {
    asm volatile("cp.async.mbarrier.arrive.noinc.shared.b64 [%0];" :: "r"(mbar) : "memory");
}
DEVFN void mbar_wait(uint32_t mbar, uint32_t parity) {
    asm volatile(
        "{\n\t.reg .pred P;\n"
        "MW_%=:\n\t"
        "mbarrier.try_wait.parity.shared.b64 P, [%0], %1;\n\t"
        "@!P bra MW_%=;\n\t}"
        :: "r"(mbar), "r"(parity) : "memory");
}

// ---------------- SMEM layout ----------------
constexpr int SM_MBAR  = 0;      // full0, full1, empty0, empty1 (8B each)
constexpr int SM_A     = 1024;
constexpr int SM_B0    = SM_A  + 65536;
constexpr int SM_B1    = SM_B0 + 65536;
constexpr int SM_TOTAL = SM_B1 + 65536;   // 197632 B

// swizzled byte offset of (row, 16B-chunk) within a 128x256 bf16 tile
DEVFN uint32_t tile_off(int row, int chunk) {
    return (uint32_t)(row * 512 + ((((chunk & 7) ^ (row & 7))) << 4) + ((chunk & 24) << 4));
}

// Load a 128x256 bf16 tile into swizzled SMEM via cp.async (16B chunks), 256 threads
DEVFN void load_tile(uint32_t sdst, const __nv_bfloat16* __restrict__ src, int tid) {
    #pragma unroll
    for (int it = 0; it < 16; ++it) {
        int idx = tid + it * 256;           // 4096 chunks total
        int row = idx >> 5;                 // 0..127
        int c   = idx & 31;                 // chunk within row
        const __nv_bfloat16* gp = src + ((size_t)row << 8) + (c << 3);
        asm volatile("cp.async.cg.shared.global [%0], [%1], 16;"
                     :: "r"(sdst + tile_off(row, c)), "l"(gp) : "memory");
    }
}

// Decode flattened job index -> (mat, rb, j, rowrem).
// Symmetric triangles are PAIR-ORDERED: pair q = row q (64-q tiles) then row 63-q
// (q+1 tiles) = 65 tiles/pair constant, so any contiguous job range crosses few
// segment boundaries regardless of where it falls.
DEVFN void decode_job(int idx, int& mat, int& rb, int& j, int& rowrem) {
    int t = idx;
    if (t < JOBS_SYM)          { mat = 0; }
    else if (t < 2 * JOBS_SYM) { mat = 1; t -= JOBS_SYM; }
    else                       { mat = 2; t -= 2 * JOBS_SYM; }
    if (mat < 2) {
        int q = t / 65, r = t - q * 65;
        int len0 = NTILES - q;            // first row of pair: rb = q, tiles j=q..63
        if (r < len0) {
            rb = q; j = q + r; rowrem = len0 - r;
        } else {
            int rr = r - len0;            // second row: rb = 63-q, tiles j=rb..63 (q+1 of them)
            rb = (NTILES - 1) - q; j = rb + rr; rowrem = (q + 1) - rr;
        }
    } else {
        rb = t >> 6; j = t & 63; rowrem = NTILES - j;
    }
}

// ---------------- Kernel 1: normalize (pre-scaled) + diagonals + RS zero ----------------
__global__ void __launch_bounds__(256) norm_kernel(const float* __restrict__ H1,
                                                   const float* __restrict__ H2) {
    if (blockIdx.x < 128) ((float*)RSg)[blockIdx.x * 256 + threadIdx.x] = 0.f;

    int row  = (blockIdx.x * 256 + threadIdx.x) >> 5;   // one row per warp
    int lane = threadIdx.x & 31;
    const float4* p1 = (const float4*)(H1 + (size_t)row * DDIM);
    const float4* p2 = (const float4*)(H2 + (size_t)row * DDIM);
    float4 x0 = p1[lane], x1 = p1[lane + 32];
    float4 y0 = p2[lane], y1 = p2[lane + 32];

    float ss1 = x0.x*x0.x + x0.y*x0.y + x0.z*x0.z + x0.w*x0.w
              + x1.x*x1.x + x1.y*x1.y + x1.z*x1.z + x1.w*x1.w;
    float ss2 = y0.x*y0.x + y0.y*y0.y + y0.z*y0.z + y0.w*y0.w
              + y1.x*y1.x + y1.y*y1.y + y1.z*y1.z + y1.w*y1.w;
    #pragma unroll
    for (int o = 16; o; o >>= 1) {
        ss1 += __shfl_xor_sync(0xFFFFFFFFu, ss1, o);
        ss2 += __shfl_xor_sync(0xFFFFFFFFu, ss2, o);
    }
    float inv1 = SQRT_SCALE / fmaxf(sqrtf(ss1), 1e-12f);
    float inv2 = SQRT_SCALE / fmaxf(sqrtf(ss2), 1e-12f);

    __nv_bfloat162 z1p[4], z2p[4];
    z1p[0] = __float22bfloat162_rn(make_float2(x0.x * inv1, x0.y * inv1));
    z1p[1] = __float22bfloat162_rn(make_float2(x0.z * inv1, x0.w * inv1));
    z1p[2] = __float22bfloat162_rn(make_float2(x1.x * inv1, x1.y * inv1));
    z1p[3] = __float22bfloat162_rn(make_float2(x1.z * inv1, x1.w * inv1));
    z2p[0] = __float22bfloat162_rn(make_float2(y0.x * inv2, y0.y * inv2));
    z2p[1] = __float22bfloat162_rn(make_float2(y0.z * inv2, y0.w * inv2));
    z2p[2] = __float22bfloat162_rn(make_float2(y1.x * inv2, y1.y * inv2));
    z2p[3] = __float22bfloat162_rn(make_float2(y1.z * inv2, y1.w * inv2));

    uint32_t* z1 = (uint32_t*)(Z1g + (size_t)row * DDIM);
    uint32_t* z2 = (uint32_t*)(Z2g + (size_t)row * DDIM);
    z1[2 * lane]          = *(uint32_t*)&z1p[0];
    z1[2 * lane + 1]      = *(uint32_t*)&z1p[1];
    z1[64 + 2 * lane]     = *(uint32_t*)&z1p[2];
    z1[64 + 2 * lane + 1] = *(uint32_t*)&z1p[3];
    z2[2 * lane]          = *(uint32_t*)&z2p[0];
    z2[2 * lane + 1]      = *(uint32_t*)&z2p[1];
    z2[64 + 2 * lane]     = *(uint32_t*)&z2p[2];
    z2[64 + 2 * lane + 1] = *(uint32_t*)&z2p[3];

    float d11 = 0.f, d22 = 0.f, d12 = 0.f;
    #pragma unroll
    for (int k = 0; k < 4; ++k) {
        float2 f1 = __bfloat1622float2(z1p[k]);
        float2 f2 = __bfloat1622float2(z2p[k]);
        d11 += f1.x * f1.x + f1.y * f1.y;
        d22 += f2.x * f2.x + f2.y * f2.y;
        d12 += f1.x * f2.x + f1.y * f2.y;
    }
    #pragma unroll
    for (int o = 16; o; o >>= 1) {
        d11 += __shfl_xor_sync(0xFFFFFFFFu, d11, o);
        d22 += __shfl_xor_sync(0xFFFFFFFFu, d22, o);
        d12 += __shfl_xor_sync(0xFFFFFFFFu, d12, o);
    }
    if (lane == 0) {
        DGg[0][row] = d11;   // log2-domain diagonals
        DGg[1][row] = d22;
        DGg[2][row] = d12;
    }
}

// ---------------- Kernel 2: R16 pipeline + pair-ordered schedule over 152 CTAs -----------
// 8 warps, 32x64 warp tiles, mbarrier-pipelined double-buffered B, epilogue after MMA.
__global__ void __launch_bounds__(NTHREADS, 1) gram_kernel() {
    extern __shared__ char smem[];
    const uint32_t sb = smem_u32(smem);
    const int tid  = threadIdx.x;
    const int wid  = tid >> 5;
    const int lane = tid & 31;
    const int wm = wid & 3;
    const int wn = wid >> 2;
    const int bx = blockIdx.x;

    const uint32_t mb_full[2]  = { sb + SM_MBAR,      sb + SM_MBAR + 8 };
    const uint32_t mb_empty[2] = { sb + SM_MBAR + 16, sb + SM_MBAR + 24 };
    if (tid == 0) {
        mbar_init(mb_full[0], NTHREADS);
        mbar_init(mb_full[1], NTHREADS);
        mbar_init(mb_empty[0], 8);
        mbar_init(mb_empty[1], 8);
    }
    int n_full[2]  = {0, 0};
    int n_empty[2] = {0, 0};

    const int l7   = lane & 7;
    const int qA_r = (lane >> 3) & 1;
    const int qA_c = (lane >> 4);
    const int qB_r = (lane >> 4);
    const int qB_c = (lane >> 3) & 1;
    const int l3   = lane & 3;
    const int g    = lane >> 2;

    const int start = bx * JOBS_ALL / NCTA;
    const int end   = (bx + 1) * JOBS_ALL / NCTA;

    int cur = start;

    while (cur < end) {
        int mat, rb, j, rowrem;
        decode_job(cur, mat, rb, j, rowrem);

        const __nv_bfloat16 *X, *Y;
        int mrow, mcol; bool sym;
        if (mat == 0)      { X = Z1g; Y = Z1g; mrow = 0; mcol = 0; sym = true; }
        else if (mat == 1) { X = Z2g; Y = Z2g; mrow = 1; mcol = 1; sym = true; }
        else               { X = Z1g; Y = Z2g; mrow = 2; mcol = 3; sym = false; }

        const int j0 = j;
        const int seg = min(end - cur, rowrem);
        const int jend = j0 + seg;

        __syncthreads();   // all warps done with previous segment's A/B; orders mbar init

        // prologue: A + first (up to) two B tiles
        load_tile(sb + SM_A, X + (size_t)rb * MT * DDIM, tid);
        {
            const int b0 = j0 & 1;
            load_tile(b0 ? sb + SM_B1 : sb + SM_B0, Y + (size_t)j0 * MT * DDIM, tid);
            cp_mbar_arrive_noinc(mb_full[b0]);
            ++n_full[b0];
            if (j0 + 1 < jend) {
                const int b1 = b0 ^ 1;
                load_tile(b1 ? sb + SM_B1 : sb + SM_B0, Y + (size_t)(j0 + 1) * MT * DDIM, tid);
                cp_mbar_arrive_noinc(mb_full[b1]);
                ++n_full[b1];
            }
        }

        float rs[4] = {0.f, 0.f, 0.f, 0.f};

        for (int jj = j0; jj < jend; ++jj) {
            const int b = jj & 1;
            const uint32_t bsm = b ? sb + SM_B1 : sb + SM_B0;

            mbar_wait(mb_full[b], (uint32_t)((n_full[b] - 1) & 1));

            float acc[2][8][4];
            #pragma unroll
            for (int ms = 0; ms < 2; ++ms)
                #pragma unroll
                for (int ns = 0; ns < 8; ++ns)
                    #pragma unroll
                    for (int c = 0; c < 4; ++c) acc[ms][ns][c] = 0.f;

            #pragma unroll
            for (int ks = 0; ks < 16; ++ks) {
                const int ch = 2 * ks;
                uint32_t a0[4], a1[4];
                {
                    int row = wm * 32 + l7 + 8 * qA_r;
                    ldm4(a0[0], a0[1], a0[2], a0[3], sb + SM_A + tile_off(row,      ch + qA_c));
                    ldm4(a1[0], a1[1], a1[2], a1[3], sb + SM_A + tile_off(row + 16, ch + qA_c));
                }
                uint32_t bf[4][4];
                #pragma unroll
                for (int np = 0; np < 4; ++np) {
                    int row = wn * 64 + np * 16 + l7 + 8 * qB_r;
                    ldm4(bf[np][0], bf[np][1], bf[np][2], bf[np][3],
                         bsm + tile_off(row, ch + qB_c));
                }
                #pragma unroll
                for (int np = 0; np < 4; ++np)
                    #pragma unroll
                    for (int sub = 0; sub < 2; ++sub) {
                        mma_bf16(acc[0][2 * np + sub], a0, bf[np][2 * sub], bf[np][2 * sub + 1]);
                        mma_bf16(acc[1][2 * np + sub], a1, bf[np][2 * sub], bf[np][2 * sub + 1]);
                    }
            }

            if (lane == 0) mbar_arrive(mb_empty[b]);
            ++n_empty[b];

            // epilogue (overlaps other warps' MMA phase)
            float col[16];
            #pragma unroll
            for (int k = 0; k < 16; ++k) col[k] = 0.f;
            #pragma unroll
            for (int ms = 0; ms < 2; ++ms)
                #pragma unroll
                for (int ns = 0; ns < 8; ++ns) {
                    float e0 = fexp2(acc[ms][ns][0]);
                    float e1 = fexp2(acc[ms][ns][1]);
                    float e2 = fexp2(acc[ms][ns][2]);
                    float e3 = fexp2(acc[ms][ns][3]);
                    rs[2 * ms]     += e0 + e1;
                    rs[2 * ms + 1] += e2 + e3;
                    col[2 * ns]     += e0 + e2;
                    col[2 * ns + 1] += e1 + e3;
                }
            if (!sym || jj != rb) {
                #pragma unroll
                for (int k = 0; k < 16; ++k) {
                    col[k] += __shfl_xor_sync(0xFFFFFFFFu, col[k], 4);
                    col[k] += __shfl_xor_sync(0xFFFFFFFFu, col[k], 8);
                    col[k] += __shfl_xor_sync(0xFFFFFFFFu, col[k], 16);
                }
                if (lane < 4) {
                    float* dst = &RSg[mcol][jj * MT + wn * 64];
                    #pragma unroll
                    for (int ns = 0; ns < 8; ++ns) {
                        atomicAdd(dst + ns * 8 + 2 * lane,     col[2 * ns]);
                        atomicAdd(dst + ns * 8 + 2 * lane + 1, col[2 * ns + 1]);
                    }
                }
            }

            // producer: refill this buffer with tile jj+2
            if (jj + 2 < jend) {
                mbar_wait(mb_empty[b], (uint32_t)((n_empty[b] - 1) & 1));
                load_tile(bsm, Y + (size_t)(jj + 2) * MT * DDIM, tid);
                cp_mbar_arrive_noinc(mb_full[b]);
                ++n_full[b];
            }
        }

        // flush row sums for this segment
        #pragma unroll
        for (int r = 0; r < 4; ++r) {
            rs[r] += __shfl_xor_sync(0xFFFFFFFFu, rs[r], 1);
            rs[r] += __shfl_xor_sync(0xFFFFFFFFu, rs[r], 2);
        }
        if (l3 == 0) {
            float* dst = &RSg[mrow][rb * MT + wm * 32];
            #pragma unroll
            for (int ms = 0; ms < 2; ++ms)
                #pragma unroll
                for (int cc = 0; cc < 2; ++cc)
                    atomicAdd(dst + ms * 16 + 8 * cc + g, rs[2 * ms + cc]);
        }

        cur += seg;
    }
}

// ---------------- Kernel 3: final reduction (1024 threads) ----------------
__global__ void __launch_bounds__(1024) reduce_kernel(float* out) {
    float s = 0.f;
    for (int i = threadIdx.x; i < NROWS; i += 1024) {
        float den1 = RSg[0][i] + RSg[2][i] - exp2f(DGg[0][i]);
        float den2 = RSg[1][i] + RSg[3][i] - exp2f(DGg[1][i]);
        s += 0.5f * (__logf(den1) + __logf(den2)) - DGg[2][i] * LN2F;
    }
    #pragma unroll
    for (int o = 16; o; o >>= 1) s += __shfl_xor_sync(0xFFFFFFFFu, s, o);
    __shared__ float ws[32];
    if ((threadIdx.x & 31) == 0) ws[threadIdx.x >> 5] = s;
    __syncthreads();
    if (threadIdx.x < 32) {
        s = ws[threadIdx.x];
        #pragma unroll
        for (int o = 16; o; o >>= 1) s += __shfl_xor_sync(0xFFFFFFFFu, s, o);
        if (threadIdx.x == 0) out[0] = s / (float)NROWS;
    }
}

// ---------------- launch ----------------
extern "C" void kernel_launch(void* const* d_in, const int* in_sizes, int n_in,
                              void* d_out, int out_size) {
    const float* H1 = (const float*)d_in[0];
    const float* H2 = (const float*)d_in[1];
    float* out = (float*)d_out;

    norm_kernel<<<NROWS * 32 / 256, 256>>>(H1, H2);

    static bool attr_set = false;
    if (!attr_set) {
        cudaFuncSetAttribute(gram_kernel, cudaFuncAttributeMaxDynamicSharedMemorySize, SM_TOTAL);
        attr_set = true;
    }
    gram_kernel<<<NCTA, NTHREADS, SM_TOTAL>>>();

    reduce_kernel<<<1, 1024>>>(out);
}